// round 15
// baseline (speedup 1.0000x reference)
#include <cuda_runtime.h>
#include <cuda_fp16.h>
#include <cstdint>
#include <math.h>

#define BB    2
#define SS    2048
#define HID   2048
#define NH    16
#define NG    4
#define DK    128
#define NHPG  4
#define BSTOK (BB*SS)
#define KDIM  2048
#define NQKV  3072     // 2048 Q + 512 K + 512 V

// ---------------------------------------------------------------------------
// Scratch (__device__ globals; allocation-free rule)
// ---------------------------------------------------------------------------
static __device__ __half g_xh  [BSTOK * KDIM];         // x fp16
static __device__ __half g_wqkv[NQKV * KDIM];          // [wq | wk | wv] transposed [N,K] fp16
static __device__ __half g_wd  [HID * KDIM];           // dense weights transposed fp16

static __device__ __half g_qh [BSTOK * HID];           // rope'd, pre-scaled Q fp16
static __device__ __half g_kh [BSTOK * NG * DK];       // rope'd K fp16 [tok][g*128+d]
static __device__ __half g_v  [BSTOK * NG * DK];       // V fp16 [tok][g*128+d]
static __device__ __half g_vth[BB * NG * DK * SS];     // V transposed fp16 [b,g][d][s]
static __device__ __half g_ch [BSTOK * KDIM];          // ctx fp16

// ---------------------------------------------------------------------------
// helpers (base-target safe)
// ---------------------------------------------------------------------------
__device__ __forceinline__ void cp_async16(uint32_t s, const void* g) {
    asm volatile("cp.async.cg.shared.global [%0], [%1], 16;\n" :: "r"(s), "l"(g) : "memory");
}
__device__ __forceinline__ void cp_commit() {
    asm volatile("cp.async.commit_group;\n" ::: "memory");
}
__device__ __forceinline__ uint32_t lds_u32(uint32_t a) {
    uint32_t v; asm("ld.shared.b32 %0, [%1];" : "=r"(v) : "r"(a)); return v;
}
__device__ __forceinline__ void ldsm4(uint32_t* r, uint32_t a) {
    asm volatile("ldmatrix.sync.aligned.m8n8.x4.shared.b16 {%0,%1,%2,%3}, [%4];"
        : "=r"(r[0]), "=r"(r[1]), "=r"(r[2]), "=r"(r[3]) : "r"(a));
}
__device__ __forceinline__ uint32_t pack2h(float lo, float hi) {
    __half2 h = __floats2half2_rn(lo, hi);
    return *(uint32_t*)&h;
}
__device__ __forceinline__ void mma16816(float* c, const uint32_t* a, const uint32_t* b)
{
    asm volatile(
        "mma.sync.aligned.m16n8k16.row.col.f32.f16.f16.f32 "
        "{%0,%1,%2,%3}, {%4,%5,%6,%7}, {%8,%9}, {%0,%1,%2,%3};"
        : "+f"(c[0]), "+f"(c[1]), "+f"(c[2]), "+f"(c[3])
        : "r"(a[0]), "r"(a[1]), "r"(a[2]), "r"(a[3]), "r"(b[0]), "r"(b[1]));
}

// ---------------------------------------------------------------------------
// Prep: fp32 -> fp16 convert
// ---------------------------------------------------------------------------
__global__ void prep_h(const float* __restrict__ src, __half* __restrict__ h, int n4)
{
    int i = blockIdx.x * blockDim.x + threadIdx.x;
    if (i >= n4) return;
    float4 v = ((const float4*)src)[i];
    __half hh[4] = {__float2half_rn(v.x), __float2half_rn(v.y),
                    __float2half_rn(v.z), __float2half_rn(v.w)};
    ((uint2*)h)[i] = *(uint2*)hh;
}

// ---------------------------------------------------------------------------
// Prep: transpose W[K, N] fp32 -> WT [N, K] fp16
// ---------------------------------------------------------------------------
__global__ void transpose_h(const float* __restrict__ W,
                            __half* __restrict__ T, int Ncols)
{
    __shared__ float tile[32][33];
    int n = blockIdx.x * 32 + threadIdx.x;
    int k0 = blockIdx.y * 32;
#pragma unroll
    for (int r = 0; r < 4; r++) {
        int k = k0 + threadIdx.y + r * 8;
        tile[threadIdx.y + r * 8][threadIdx.x] = W[(size_t)k * Ncols + n];
    }
    __syncthreads();
#pragma unroll
    for (int r = 0; r < 4; r++) {
        int nn = blockIdx.x * 32 + threadIdx.y + r * 8;
        int kk = k0 + threadIdx.x;
        T[(size_t)nn * KDIM + kk] = __float2half_rn(tile[threadIdx.x][threadIdx.y + r * 8]);
    }
}

// ---------------------------------------------------------------------------
// GEMM mainloop shared bits. Tile 128x128, 8 warps (2M x 4N), 3-stage cp.async.
// ---------------------------------------------------------------------------
#define LDB    144
#define TILEB  (128 * LDB)
#define STAGEB (2 * TILEB)          // A | B
#define GEMM_SMEM (3 * STAGEB)      // 110592 B

__device__ __forceinline__ void load_chunk_mma(
    const __half* __restrict__ A, const __half* __restrict__ Bm,
    int m0, int n0, int k0, uint32_t stage, int tid)
{
#pragma unroll
    for (int i = 0; i < 8; i++) {
        int lin = i * 256 + tid;            // 0..2047
        int t   = lin >> 10;                // 0:A 1:B
        int rem = lin & 1023;
        int row = rem >> 3;
        int c   = rem & 7;
        const __half* base = t ? Bm : A;
        int grow = (t ? n0 : m0) + row;
        cp_async16(stage + t * TILEB + row * LDB + c * 16,
                   base + (size_t)grow * KDIM + k0 + c * 8);
    }
    cp_commit();
}

// mainloop macro body as function computing acc
#define GEMM_MAINLOOP(A, Bm)                                                   \
    const int NC = KDIM / 64;                                                  \
    load_chunk_mma(A, Bm, m0, n0, 0, sb, tid);                                 \
    load_chunk_mma(A, Bm, m0, n0, 64, sb + STAGEB, tid);                       \
    for (int c = 0; c < NC; c++) {                                             \
        if (c + 1 < NC) {                                                      \
            asm volatile("cp.async.wait_group 1;\n" ::: "memory");             \
        } else {                                                               \
            asm volatile("cp.async.wait_group 0;\n" ::: "memory");             \
        }                                                                      \
        __syncthreads();                                                       \
        if (c + 2 < NC)                                                        \
            load_chunk_mma(A, Bm, m0, n0, (c + 2) * 64,                        \
                           sb + (uint32_t)((c + 2) % 3) * STAGEB, tid);        \
        const uint32_t stg = sb + (uint32_t)(c % 3) * STAGEB;                  \
        _Pragma("unroll")                                                      \
        for (int ks = 0; ks < 4; ks++) {                                       \
            const uint32_t koff = (uint32_t)ks * 32;                           \
            uint32_t ah[4][4], bm2[2][4];                                      \
            _Pragma("unroll")                                                  \
            for (int mt = 0; mt < 4; mt++)                                     \
                ldsm4(ah[mt], stg + aBase + (uint32_t)mt * (16 * LDB) + koff); \
            _Pragma("unroll")                                                  \
            for (int p = 0; p < 2; p++)                                        \
                ldsm4(bm2[p], stg + TILEB + bBase + (uint32_t)p * (16 * LDB) + koff); \
            _Pragma("unroll")                                                  \
            for (int mt = 0; mt < 4; mt++)                                     \
                _Pragma("unroll")                                              \
                for (int nt = 0; nt < 4; nt++)                                 \
                    mma16816(acc[mt][nt], ah[mt], &bm2[nt >> 1][(nt & 1) * 2]);\
        }                                                                      \
    }

// ---------------------------------------------------------------------------
// Dense GEMM: plain fp32 output (C = ctx @ wd -> d_out)
// ---------------------------------------------------------------------------
__global__ __launch_bounds__(256) void gemm_mma(
    const __half* __restrict__ A, const __half* __restrict__ Bm,
    float* __restrict__ C, int N)
{
    extern __shared__ char smc[];
    uint32_t sb = (uint32_t)__cvta_generic_to_shared(smc);
    const int tid  = threadIdx.x;
    const int wid  = tid >> 5;
    const int lane = tid & 31;
    const int wm = wid >> 2;
    const int wn = wid & 3;
    const int m0 = blockIdx.y * 128;
    const int n0 = blockIdx.x * 128;
    const int r  = lane >> 2;
    const int kq = (lane & 3) * 2;
    const int qd = lane >> 3, lr = lane & 7;
    const uint32_t aBase = (uint32_t)((wm * 64 + (qd & 1) * 8 + lr) * LDB + (qd >> 1) * 16);
    const uint32_t bBase = (uint32_t)((wn * 32 + (qd >> 1) * 8 + lr) * LDB + (qd & 1) * 16);

    float acc[4][4][4];
#pragma unroll
    for (int mt = 0; mt < 4; mt++)
#pragma unroll
        for (int nt = 0; nt < 4; nt++)
#pragma unroll
            for (int j = 0; j < 4; j++) acc[mt][nt][j] = 0.0f;

    GEMM_MAINLOOP(A, Bm)

#pragma unroll
    for (int mt = 0; mt < 4; mt++) {
#pragma unroll
        for (int nt = 0; nt < 4; nt++) {
            int row = m0 + wm * 64 + mt * 16 + r;
            int col = n0 + wn * 32 + nt * 8 + kq;
            *(float2*)&C[(size_t)row * N + col]       = make_float2(acc[mt][nt][0], acc[mt][nt][1]);
            *(float2*)&C[(size_t)(row + 8) * N + col] = make_float2(acc[mt][nt][2], acc[mt][nt][3]);
        }
    }
}

// ---------------------------------------------------------------------------
// QKV GEMM with fused rope/scale/fp16 epilogue. N fixed = NQKV.
// Tile n0 < 2048: Q head; [2048,2560): K group; [2560,3072): V group.
// ---------------------------------------------------------------------------
#define QSCALE 0.08838834764831845f
#define LDS_S  132

__global__ __launch_bounds__(256) void gemm_qkv(
    const __half* __restrict__ A, const __half* __restrict__ Bm)
{
    extern __shared__ char smc[];
    uint32_t sb = (uint32_t)__cvta_generic_to_shared(smc);
    const int tid  = threadIdx.x;
    const int wid  = tid >> 5;
    const int lane = tid & 31;
    const int wm = wid >> 2;
    const int wn = wid & 3;
    const int m0 = blockIdx.y * 128;
    const int n0 = blockIdx.x * 128;
    const int r  = lane >> 2;
    const int kq = (lane & 3) * 2;
    const int qd = lane >> 3, lr = lane & 7;
    const uint32_t aBase = (uint32_t)((wm * 64 + (qd & 1) * 8 + lr) * LDB + (qd >> 1) * 16);
    const uint32_t bBase = (uint32_t)((wn * 32 + (qd >> 1) * 8 + lr) * LDB + (qd & 1) * 16);

    float acc[4][4][4];
#pragma unroll
    for (int mt = 0; mt < 4; mt++)
#pragma unroll
        for (int nt = 0; nt < 4; nt++)
#pragma unroll
            for (int j = 0; j < 4; j++) acc[mt][nt][j] = 0.0f;

    GEMM_MAINLOOP(A, Bm)

    // ---- stage acc to smem fp32, then rope/convert epilogue ----
    float* S = (float*)smc;
    __syncthreads();
#pragma unroll
    for (int mt = 0; mt < 4; mt++) {
#pragma unroll
        for (int nt = 0; nt < 4; nt++) {
            int row = wm * 64 + mt * 16 + r;
            int col = wn * 32 + nt * 8 + kq;
            *(float2*)&S[row * LDS_S + col]       = make_float2(acc[mt][nt][0], acc[mt][nt][1]);
            *(float2*)&S[(row + 8) * LDS_S + col] = make_float2(acc[mt][nt][2], acc[mt][nt][3]);
        }
    }
    __syncthreads();

    const bool isV = (n0 >= 2560);
    const float scale = (n0 < 2048) ? QSCALE : 1.0f;

    for (int it = tid; it < 128 * 32; it += 256) {
        int row = it >> 5;
        int d0  = (it & 31) * 2;
        int tokg = m0 + row;
        float a0 = S[row * LDS_S + d0],      a1 = S[row * LDS_S + d0 + 1];
        float b0 = S[row * LDS_S + d0 + 64], b1 = S[row * LDS_S + d0 + 65];
        uint32_t w0, w1;
        if (isV) {
            w0 = pack2h(a0, a1);
            w1 = pack2h(b0, b1);
        } else {
            int t = tokg & (SS - 1);
            float f0 = (float)t * exp2f(-0.20762050593045935f * (float)d0);
            float f1 = (float)t * exp2f(-0.20762050593045935f * (float)(d0 + 1));
            float c0, s0, c1, s1;
            sincosf(f0, &s0, &c0);
            sincosf(f1, &s1, &c1);
            w0 = pack2h((a0 * c0 - b0 * s0) * scale, (a1 * c1 - b1 * s1) * scale);
            w1 = pack2h((b0 * c0 + a0 * s0) * scale, (b1 * c1 + a1 * s1) * scale);
        }
        __half* dst;
        size_t off;
        if (n0 < 2048) {
            dst = g_qh;
            off = (size_t)tokg * HID + (n0 & ~127) + d0;        // n0 = h*128
        } else if (n0 < 2560) {
            dst = g_kh;
            off = (size_t)tokg * (NG * DK) + (n0 - 2048) + d0;  // (g*128)+d
        } else {
            dst = g_v;
            off = (size_t)tokg * (NG * DK) + (n0 - 2560) + d0;
        }
        *(uint32_t*)&dst[off]      = w0;
        *(uint32_t*)&dst[off + 64] = w1;
    }
}

// ---------------------------------------------------------------------------
// V transpose fp16 -> fp16 [b,g][d][s]
// ---------------------------------------------------------------------------
__global__ void vt_h()   // grid (SS/32, DK/32, BB*NG), block (32,8)
{
    __shared__ __half tile[32][33];
    int bg = blockIdx.z;
    int b  = bg >> 2, g = bg & 3;
    int s0 = blockIdx.x * 32, d0 = blockIdx.y * 32;
#pragma unroll
    for (int r = 0; r < 4; r++) {
        int s = s0 + threadIdx.y + r * 8;
        tile[threadIdx.y + r * 8][threadIdx.x] =
            g_v[(size_t)(b * SS + s) * (NG * DK) + g * DK + d0 + threadIdx.x];
    }
    __syncthreads();
#pragma unroll
    for (int r = 0; r < 4; r++) {
        int d = d0 + threadIdx.y + r * 8;
        int s = s0 + threadIdx.x;
        g_vth[((size_t)bg * DK + d) * SS + s] = tile[threadIdx.x][threadIdx.y + r * 8];
    }
}

// ---------------------------------------------------------------------------
// Flash attention fp16: QK 1 term, PV 1 term, causal. fp32 softmax/accum.
// ---------------------------------------------------------------------------
#define FQT 128
#define FKT 64
#define OFF_Q  0
#define STG0   (FQT*272)
#define STG_K  0
#define STG_V  (FKT*272)
#define STG_SZ (FKT*272 + FQT*144)
#define FLASH_SMEM (STG0 + 2*STG_SZ)     // 106496

__device__ __forceinline__ void flash_load_kv(int b, int g, int kbase, uint32_t stg, int tid)
{
#pragma unroll
    for (int i = 0; i < 8; i++) {
        int lin = i * 256 + tid;
        if (lin < 1024) {                 // K tile: 64 rows x 16 chunks
            int row = lin >> 4, c = lin & 15;
            const __half* src = g_kh
                + (size_t)(b * SS + kbase + row) * (NG * DK) + g * DK + c * 8;
            cp_async16(stg + STG_K + row * 272 + c * 16, src);
        } else {                          // Vt tile: 128 rows x 8 chunks
            int lin2 = lin - 1024;
            int row = lin2 >> 3, c = lin2 & 7;
            const __half* src = g_vth
                + ((size_t)(b * NG + g) * DK + row) * SS + kbase + c * 8;
            cp_async16(stg + STG_V + row * 144 + c * 16, src);
        }
    }
    cp_commit();
}

__global__ __launch_bounds__(256) void flash_tc()
{
    extern __shared__ char smc[];
    uint32_t sb = (uint32_t)__cvta_generic_to_shared(smc);
    const int tid  = threadIdx.x;
    const int wid  = tid >> 5;
    const int lane = tid & 31;
    const int qt = gridDim.x - 1 - blockIdx.x;    // heavy tiles first
    const int h  = blockIdx.y;
    const int b  = blockIdx.z;
    const int g  = h / NHPG;
    const int q0 = qt * FQT;
    const int r  = lane >> 2;
    const int kq = (lane & 3) * 2;

#pragma unroll
    for (int i = 0; i < 8; i++) {
        int lin = i * 256 + tid;
        int row = lin >> 4, c = lin & 15;
        const __half* src = g_qh + (size_t)(b * SS + q0 + row) * HID + h * DK + c * 8;
        cp_async16(sb + OFF_Q + row * 272 + c * 16, src);
    }
    cp_commit();

    const int numc = 2 * (qt + 1);
    flash_load_kv(b, g, 0, sb + STG0, tid);

    float m0 = -1e30f, m1 = -1e30f, l0 = 0.0f, l1 = 0.0f;
    float acc[16][4];
#pragma unroll
    for (int nt2 = 0; nt2 < 16; nt2++)
#pragma unroll
        for (int j = 0; j < 4; j++) acc[nt2][j] = 0.0f;

    const uint32_t qh_base = sb + OFF_Q + (wid * 16 + r) * 272 + kq * 2;

    for (int kc = 0; kc < numc; kc++) {
        const uint32_t stg = sb + STG0 + (uint32_t)(kc & 1) * STG_SZ;
        const int kbase = kc * FKT;
        if (kc + 1 < numc) {
            flash_load_kv(b, g, (kc + 1) * FKT, sb + STG0 + (uint32_t)((kc + 1) & 1) * STG_SZ, tid);
            asm volatile("cp.async.wait_group 1;\n" ::: "memory");
        } else {
            asm volatile("cp.async.wait_group 0;\n" ::: "memory");
        }
        __syncthreads();

        float sc[8][4];
#pragma unroll
        for (int nt = 0; nt < 8; nt++)
#pragma unroll
            for (int j = 0; j < 4; j++) sc[nt][j] = 0.0f;

#pragma unroll
        for (int kd = 0; kd < 8; kd++) {
            uint32_t ah[4];
            uint32_t qa = qh_base + kd * 32;
            ah[0] = lds_u32(qa);
            ah[1] = lds_u32(qa + 8 * 272);
            ah[2] = lds_u32(qa + 16);
            ah[3] = lds_u32(qa + 8 * 272 + 16);
#pragma unroll
            for (int nt = 0; nt < 8; nt++) {
                uint32_t kb = stg + STG_K + (nt * 8 + r) * 272 + kq * 2 + kd * 32;
                uint32_t bm[2] = {lds_u32(kb), lds_u32(kb + 16)};
                mma16816(sc[nt], ah, bm);
            }
        }

        if (kbase + FKT > q0) {
            const int row0g = q0 + wid * 16 + r;
#pragma unroll
            for (int nt = 0; nt < 8; nt++) {
                int key = kbase + nt * 8 + kq;
                if (key     > row0g)     sc[nt][0] = -1e30f;
                if (key + 1 > row0g)     sc[nt][1] = -1e30f;
                if (key     > row0g + 8) sc[nt][2] = -1e30f;
                if (key + 1 > row0g + 8) sc[nt][3] = -1e30f;
            }
        }

        float mx0 = -1e30f, mx1 = -1e30f;
#pragma unroll
        for (int nt = 0; nt < 8; nt++) {
            mx0 = fmaxf(mx0, fmaxf(sc[nt][0], sc[nt][1]));
            mx1 = fmaxf(mx1, fmaxf(sc[nt][2], sc[nt][3]));
        }
        mx0 = fmaxf(mx0, __shfl_xor_sync(0xffffffffu, mx0, 1));
        mx0 = fmaxf(mx0, __shfl_xor_sync(0xffffffffu, mx0, 2));
        mx1 = fmaxf(mx1, __shfl_xor_sync(0xffffffffu, mx1, 1));
        mx1 = fmaxf(mx1, __shfl_xor_sync(0xffffffffu, mx1, 2));
        float mn0 = fmaxf(m0, mx0), mn1 = fmaxf(m1, mx1);
        float c0 = __expf(m0 - mn0), c1 = __expf(m1 - mn1);
        float sum0 = 0.0f, sum1 = 0.0f;
#pragma unroll
        for (int nt = 0; nt < 8; nt++) {
            sc[nt][0] = __expf(sc[nt][0] - mn0); sum0 += sc[nt][0];
            sc[nt][1] = __expf(sc[nt][1] - mn0); sum0 += sc[nt][1];
            sc[nt][2] = __expf(sc[nt][2] - mn1); sum1 += sc[nt][2];
            sc[nt][3] = __expf(sc[nt][3] - mn1); sum1 += sc[nt][3];
        }
        sum0 += __shfl_xor_sync(0xffffffffu, sum0, 1);
        sum0 += __shfl_xor_sync(0xffffffffu, sum0, 2);
        sum1 += __shfl_xor_sync(0xffffffffu, sum1, 1);
        sum1 += __shfl_xor_sync(0xffffffffu, sum1, 2);
        l0 = l0 * c0 + sum0;  m0 = mn0;
        l1 = l1 * c1 + sum1;  m1 = mn1;
#pragma unroll
        for (int nt2 = 0; nt2 < 16; nt2++) {
            acc[nt2][0] *= c0; acc[nt2][1] *= c0;
            acc[nt2][2] *= c1; acc[nt2][3] *= c1;
        }

#pragma unroll
        for (int kk = 0; kk < 4; kk++) {
            uint32_t ph[4];
#pragma unroll
            for (int t4 = 0; t4 < 4; t4++) {
                int nt = 2 * kk + (t4 >> 1);
                ph[t4] = pack2h(sc[nt][(t4 & 1) * 2], sc[nt][(t4 & 1) * 2 + 1]);
            }
#pragma unroll
            for (int nt2 = 0; nt2 < 16; nt2++) {
                uint32_t vb = stg + STG_V + (nt2 * 8 + r) * 144 + (kk * 16 + kq) * 2;
                uint32_t bm[2] = {lds_u32(vb), lds_u32(vb + 16)};
                mma16816(acc[nt2], ph, bm);
            }
        }
        __syncthreads();
    }

    float inv0 = 1.0f / l0, inv1 = 1.0f / l1;
    size_t row0 = (size_t)(b * SS + q0 + wid * 16 + r);
    size_t row1 = row0 + 8;
#pragma unroll
    for (int nt2 = 0; nt2 < 16; nt2++) {
        int d = h * DK + nt2 * 8 + kq;
        *(uint32_t*)&g_ch[row0 * HID + d] = pack2h(acc[nt2][0] * inv0, acc[nt2][1] * inv0);
        *(uint32_t*)&g_ch[row1 * HID + d] = pack2h(acc[nt2][2] * inv1, acc[nt2][3] * inv1);
    }
}

// ---------------------------------------------------------------------------
extern "C" void kernel_launch(void* const* d_in, const int* in_sizes, int n_in,
                              void* d_out, int out_size)
{
    const float* x       = (const float*)d_in[0];
    const float* w_q     = (const float*)d_in[1];
    const float* w_kv    = (const float*)d_in[2];
    const float* w_dense = (const float*)d_in[3];
    float* out = (float*)d_out;

    __half *xh, *wqkv, *wd, *ch;
    cudaGetSymbolAddress((void**)&xh,   g_xh);
    cudaGetSymbolAddress((void**)&wqkv, g_wqkv);
    cudaGetSymbolAddress((void**)&wd,   g_wd);
    cudaGetSymbolAddress((void**)&ch,   g_ch);

    cudaFuncSetAttribute(gemm_mma, cudaFuncAttributeMaxDynamicSharedMemorySize, GEMM_SMEM);
    cudaFuncSetAttribute(gemm_qkv, cudaFuncAttributeMaxDynamicSharedMemorySize, GEMM_SMEM);
    cudaFuncSetAttribute(flash_tc, cudaFuncAttributeMaxDynamicSharedMemorySize, FLASH_SMEM);

    // prep: convert x; transpose weights into combined buffer
    prep_h<<<(BSTOK * KDIM / 4 + 255) / 256, 256>>>(x, xh, BSTOK * KDIM / 4);
    transpose_h<<<dim3(HID / 32, KDIM / 32), dim3(32, 8)>>>(w_q, wqkv, HID);
    transpose_h<<<dim3((2 * NG * DK) / 32, KDIM / 32), dim3(32, 8)>>>(w_kv, wqkv + (size_t)2048 * KDIM, 2 * NG * DK);
    transpose_h<<<dim3(HID / 32, KDIM / 32), dim3(32, 8)>>>(w_dense, wd, HID);

    // fused QKV projection (rope/scale/fp16 in epilogue)
    gemm_qkv<<<dim3(NQKV / 128, BSTOK / 128), 256, GEMM_SMEM>>>(xh, wqkv);

    // V transpose
    vt_h<<<dim3(SS / 32, DK / 32, BB * NG), dim3(32, 8)>>>();

    // attention (tensor cores, fp16)
    flash_tc<<<dim3(SS / FQT, NH, BB), 256, FLASH_SMEM>>>();

    // dense projection
    gemm_mma<<<dim3(HID / 128, BSTOK / 128), 256, GEMM_SMEM>>>(ch, wd, out, HID);
}

// round 16
// speedup vs baseline: 1.5188x; 1.5188x over previous
#include <cuda_runtime.h>
#include <cuda_fp16.h>
#include <cstdint>
#include <math.h>

#define BB    2
#define SS    2048
#define HID   2048
#define NH    16
#define NG    4
#define DK    128
#define NHPG  4
#define BSTOK (BB*SS)
#define KDIM  2048
#define NQKV  3072     // 2048 Q + 512 K + 512 V

// ---------------------------------------------------------------------------
// Scratch (__device__ globals; allocation-free rule)
// ---------------------------------------------------------------------------
static __device__ float  g_qkv [BSTOK * NQKV];         // QKV proj fp32 [tok][3072]

static __device__ __half g_xh  [BSTOK * KDIM];         // x fp16
static __device__ __half g_wqkv[NQKV * KDIM];          // [wq|wk|wv] transposed [N,K] fp16
static __device__ __half g_wd  [HID * KDIM];           // dense weights transposed fp16

static __device__ __half g_qh [BSTOK * HID];           // rope'd, pre-scaled Q fp16
static __device__ __half g_kh [BSTOK * NG * DK];       // rope'd K fp16 [tok][g*128+d]
static __device__ __half g_vth[BB * NG * DK * SS];     // V transposed fp16 [b,g][d][s]
static __device__ __half g_ch [BSTOK * KDIM];          // ctx fp16

// ---------------------------------------------------------------------------
// helpers (base-target safe)
// ---------------------------------------------------------------------------
__device__ __forceinline__ void cp_async16(uint32_t s, const void* g) {
    asm volatile("cp.async.cg.shared.global [%0], [%1], 16;\n" :: "r"(s), "l"(g) : "memory");
}
__device__ __forceinline__ void cp_commit() {
    asm volatile("cp.async.commit_group;\n" ::: "memory");
}
__device__ __forceinline__ uint32_t lds_u32(uint32_t a) {
    uint32_t v; asm("ld.shared.b32 %0, [%1];" : "=r"(v) : "r"(a)); return v;
}
__device__ __forceinline__ void ldsm4(uint32_t* r, uint32_t a) {
    asm volatile("ldmatrix.sync.aligned.m8n8.x4.shared.b16 {%0,%1,%2,%3}, [%4];"
        : "=r"(r[0]), "=r"(r[1]), "=r"(r[2]), "=r"(r[3]) : "r"(a));
}
__device__ __forceinline__ uint32_t pack2h(float lo, float hi) {
    __half2 h = __floats2half2_rn(lo, hi);
    return *(uint32_t*)&h;
}
__device__ __forceinline__ void mma16816(float* c, const uint32_t* a, const uint32_t* b)
{
    asm volatile(
        "mma.sync.aligned.m16n8k16.row.col.f32.f16.f16.f32 "
        "{%0,%1,%2,%3}, {%4,%5,%6,%7}, {%8,%9}, {%0,%1,%2,%3};"
        : "+f"(c[0]), "+f"(c[1]), "+f"(c[2]), "+f"(c[3])
        : "r"(a[0]), "r"(a[1]), "r"(a[2]), "r"(a[3]), "r"(b[0]), "r"(b[1]));
}

// ---------------------------------------------------------------------------
// Prep: fp32 -> fp16 convert
// ---------------------------------------------------------------------------
__global__ void prep_h(const float* __restrict__ src, __half* __restrict__ h, int n4)
{
    int i = blockIdx.x * blockDim.x + threadIdx.x;
    if (i >= n4) return;
    float4 v = ((const float4*)src)[i];
    __half hh[4] = {__float2half_rn(v.x), __float2half_rn(v.y),
                    __float2half_rn(v.z), __float2half_rn(v.w)};
    ((uint2*)h)[i] = *(uint2*)hh;
}

// ---------------------------------------------------------------------------
// Prep: transpose W[K, N] fp32 -> WT [N, K] fp16
// ---------------------------------------------------------------------------
__global__ void transpose_h(const float* __restrict__ W,
                            __half* __restrict__ T, int Ncols)
{
    __shared__ float tile[32][33];
    int n = blockIdx.x * 32 + threadIdx.x;
    int k0 = blockIdx.y * 32;
#pragma unroll
    for (int r = 0; r < 4; r++) {
        int k = k0 + threadIdx.y + r * 8;
        tile[threadIdx.y + r * 8][threadIdx.x] = W[(size_t)k * Ncols + n];
    }
    __syncthreads();
#pragma unroll
    for (int r = 0; r < 4; r++) {
        int nn = blockIdx.x * 32 + threadIdx.y + r * 8;
        int kk = k0 + threadIdx.x;
        T[(size_t)nn * KDIM + kk] = __float2half_rn(tile[threadIdx.x][threadIdx.y + r * 8]);
    }
}

// ---------------------------------------------------------------------------
// mma.sync GEMM: C = A @ B, both single fp16, fp32 accum.
// Tile 128x128, 8 warps (2M x 4N), 3-stage cp.async + ldmatrix.
// ---------------------------------------------------------------------------
#define LDB    144
#define TILEB  (128 * LDB)
#define STAGEB (2 * TILEB)          // A | B
#define GEMM_SMEM (3 * STAGEB)      // 110592 B

__device__ __forceinline__ void load_chunk_mma(
    const __half* __restrict__ A, const __half* __restrict__ Bm,
    int m0, int n0, int k0, uint32_t stage, int tid)
{
#pragma unroll
    for (int i = 0; i < 8; i++) {
        int lin = i * 256 + tid;            // 0..2047
        int t   = lin >> 10;                // 0:A 1:B
        int rem = lin & 1023;
        int row = rem >> 3;
        int c   = rem & 7;
        const __half* base = t ? Bm : A;
        int grow = (t ? n0 : m0) + row;
        cp_async16(stage + t * TILEB + row * LDB + c * 16,
                   base + (size_t)grow * KDIM + k0 + c * 8);
    }
    cp_commit();
}

__global__ __launch_bounds__(256) void gemm_mma(
    const __half* __restrict__ A, const __half* __restrict__ Bm,
    float* __restrict__ C, int N)
{
    extern __shared__ char smc[];
    uint32_t sb = (uint32_t)__cvta_generic_to_shared(smc);
    const int tid  = threadIdx.x;
    const int wid  = tid >> 5;
    const int lane = tid & 31;
    const int wm = wid >> 2;
    const int wn = wid & 3;
    const int m0 = blockIdx.y * 128;
    const int n0 = blockIdx.x * 128;
    const int r  = lane >> 2;
    const int kq = (lane & 3) * 2;

    const int qd = lane >> 3, lr = lane & 7;
    const uint32_t aBase = (uint32_t)((wm * 64 + (qd & 1) * 8 + lr) * LDB + (qd >> 1) * 16);
    const uint32_t bBase = (uint32_t)((wn * 32 + (qd >> 1) * 8 + lr) * LDB + (qd & 1) * 16);

    float acc[4][4][4];
#pragma unroll
    for (int mt = 0; mt < 4; mt++)
#pragma unroll
        for (int nt = 0; nt < 4; nt++)
#pragma unroll
            for (int j = 0; j < 4; j++) acc[mt][nt][j] = 0.0f;

    const int NC = KDIM / 64;           // 32
    load_chunk_mma(A, Bm, m0, n0, 0, sb, tid);
    load_chunk_mma(A, Bm, m0, n0, 64, sb + STAGEB, tid);

    for (int c = 0; c < NC; c++) {
        if (c + 1 < NC) {
            asm volatile("cp.async.wait_group 1;\n" ::: "memory");
        } else {
            asm volatile("cp.async.wait_group 0;\n" ::: "memory");
        }
        __syncthreads();
        if (c + 2 < NC)
            load_chunk_mma(A, Bm, m0, n0, (c + 2) * 64,
                           sb + (uint32_t)((c + 2) % 3) * STAGEB, tid);

        const uint32_t stg = sb + (uint32_t)(c % 3) * STAGEB;

#pragma unroll
        for (int ks = 0; ks < 4; ks++) {
            const uint32_t koff = (uint32_t)ks * 32;
            uint32_t ah[4][4], bm[2][4];
#pragma unroll
            for (int mt = 0; mt < 4; mt++)
                ldsm4(ah[mt], stg + aBase + (uint32_t)mt * (16 * LDB) + koff);
#pragma unroll
            for (int p = 0; p < 2; p++)
                ldsm4(bm[p], stg + TILEB + bBase + (uint32_t)p * (16 * LDB) + koff);

#pragma unroll
            for (int mt = 0; mt < 4; mt++)
#pragma unroll
                for (int nt = 0; nt < 4; nt++)
                    mma16816(acc[mt][nt], ah[mt], &bm[nt >> 1][(nt & 1) * 2]);
        }
    }

#pragma unroll
    for (int mt = 0; mt < 4; mt++) {
#pragma unroll
        for (int nt = 0; nt < 4; nt++) {
            int row = m0 + wm * 64 + mt * 16 + r;
            int col = n0 + wn * 32 + nt * 8 + kq;
            *(float2*)&C[(size_t)row * N + col]       = make_float2(acc[mt][nt][0], acc[mt][nt][1]);
            *(float2*)&C[(size_t)(row + 8) * N + col] = make_float2(acc[mt][nt][2], acc[mt][nt][3]);
        }
    }
}

// ---------------------------------------------------------------------------
// RoPE (Q and K merged) reading fp32 g_qkv, writing fp16 g_qh / g_kh
// ---------------------------------------------------------------------------
#define QSCALE 0.08838834764831845f

__global__ void rope_qk()
{
    int idx = blockIdx.x * blockDim.x + threadIdx.x;
    const int NQ = BSTOK * NH * 64;           // 4M Q pairs
    if (idx < NQ) {
        int j   = idx & 63;
        int h   = (idx >> 6) & (NH - 1);
        int tok = idx >> 10;
        int t = tok & (SS - 1);
        size_t src = (size_t)tok * NQKV + h * DK + j;
        float x1 = g_qkv[src], x2 = g_qkv[src + 64];
        float invf = exp2f(-0.20762050593045935f * (float)j);
        float f = (float)t * invf;
        float c, s;
        sincosf(f, &s, &c);
        size_t dst = (size_t)tok * HID + h * DK + j;
        g_qh[dst]      = __float2half_rn((x1 * c - x2 * s) * QSCALE);
        g_qh[dst + 64] = __float2half_rn((x2 * c + x1 * s) * QSCALE);
    } else {
        idx -= NQ;
        if (idx >= BSTOK * NG * 64) return;
        int j   = idx & 63;
        int g   = (idx >> 6) & (NG - 1);
        int tok = idx >> 8;
        int t = tok & (SS - 1);
        size_t src = (size_t)tok * NQKV + 2048 + g * DK + j;
        float x1 = g_qkv[src], x2 = g_qkv[src + 64];
        float invf = exp2f(-0.20762050593045935f * (float)j);
        float f = (float)t * invf;
        float c, s;
        sincosf(f, &s, &c);
        size_t dst = (size_t)tok * (NG * DK) + g * DK + j;
        g_kh[dst]      = __float2half_rn(x1 * c - x2 * s);
        g_kh[dst + 64] = __float2half_rn(x2 * c + x1 * s);
    }
}

// ---------------------------------------------------------------------------
// V transpose: fp32 g_qkv V-columns -> fp16 [b,g][d][s]
// ---------------------------------------------------------------------------
__global__ void vt_h()   // grid (SS/32, DK/32, BB*NG), block (32,8)
{
    __shared__ float tile[32][33];
    int bg = blockIdx.z;
    int b  = bg >> 2, g = bg & 3;
    int s0 = blockIdx.x * 32, d0 = blockIdx.y * 32;
#pragma unroll
    for (int r = 0; r < 4; r++) {
        int s = s0 + threadIdx.y + r * 8;
        tile[threadIdx.y + r * 8][threadIdx.x] =
            g_qkv[(size_t)(b * SS + s) * NQKV + 2560 + g * DK + d0 + threadIdx.x];
    }
    __syncthreads();
#pragma unroll
    for (int r = 0; r < 4; r++) {
        int d = d0 + threadIdx.y + r * 8;
        int s = s0 + threadIdx.x;
        size_t dst = ((size_t)bg * DK + d) * SS + s;
        g_vth[dst] = __float2half_rn(tile[threadIdx.x][threadIdx.y + r * 8]);
    }
}

// ---------------------------------------------------------------------------
// Flash attention fp16: QK 1 term, PV 1 term, causal. fp32 softmax/accum.
// Block: 256 thr = 8 warps, each warp 16 query rows. 128 q x 64 k tiles.
// ---------------------------------------------------------------------------
#define FQT 128
#define FKT 64
#define OFF_Q  0
#define STG0   (FQT*272)                 // 34816
#define STG_K  0
#define STG_V  (FKT*272)                 // 17408
#define STG_SZ (FKT*272 + FQT*144)       // 35840
#define FLASH_SMEM (STG0 + 2*STG_SZ)     // 106496

__device__ __forceinline__ void flash_load_kv(int b, int g, int kbase, uint32_t stg, int tid)
{
#pragma unroll
    for (int i = 0; i < 8; i++) {
        int lin = i * 256 + tid;
        if (lin < 1024) {                 // K tile: 64 rows x 16 chunks
            int row = lin >> 4, c = lin & 15;
            const __half* src = g_kh
                + (size_t)(b * SS + kbase + row) * (NG * DK) + g * DK + c * 8;
            cp_async16(stg + STG_K + row * 272 + c * 16, src);
        } else {                          // Vt tile: 128 rows x 8 chunks
            int lin2 = lin - 1024;
            int row = lin2 >> 3, c = lin2 & 7;
            const __half* src = g_vth
                + ((size_t)(b * NG + g) * DK + row) * SS + kbase + c * 8;
            cp_async16(stg + STG_V + row * 144 + c * 16, src);
        }
    }
    cp_commit();
}

__global__ __launch_bounds__(256) void flash_tc()
{
    extern __shared__ char smc[];
    uint32_t sb = (uint32_t)__cvta_generic_to_shared(smc);
    const int tid  = threadIdx.x;
    const int wid  = tid >> 5;
    const int lane = tid & 31;
    const int qt = gridDim.x - 1 - blockIdx.x;    // heavy tiles first
    const int h  = blockIdx.y;
    const int b  = blockIdx.z;
    const int g  = h / NHPG;
    const int q0 = qt * FQT;
    const int r  = lane >> 2;
    const int kq = (lane & 3) * 2;

    // load Q tile (once): 128 rows x 16 chunks = 2048
#pragma unroll
    for (int i = 0; i < 8; i++) {
        int lin = i * 256 + tid;
        int row = lin >> 4, c = lin & 15;
        const __half* src = g_qh + (size_t)(b * SS + q0 + row) * HID + h * DK + c * 8;
        cp_async16(sb + OFF_Q + row * 272 + c * 16, src);
    }
    cp_commit();

    const int numc = 2 * (qt + 1);
    flash_load_kv(b, g, 0, sb + STG0, tid);

    float m0 = -1e30f, m1 = -1e30f, l0 = 0.0f, l1 = 0.0f;
    float acc[16][4];
#pragma unroll
    for (int nt2 = 0; nt2 < 16; nt2++)
#pragma unroll
        for (int j = 0; j < 4; j++) acc[nt2][j] = 0.0f;

    const uint32_t qh_base = sb + OFF_Q + (wid * 16 + r) * 272 + kq * 2;

    for (int kc = 0; kc < numc; kc++) {
        const uint32_t stg = sb + STG0 + (uint32_t)(kc & 1) * STG_SZ;
        const int kbase = kc * FKT;
        if (kc + 1 < numc) {
            flash_load_kv(b, g, (kc + 1) * FKT, sb + STG0 + (uint32_t)((kc + 1) & 1) * STG_SZ, tid);
            asm volatile("cp.async.wait_group 1;\n" ::: "memory");
        } else {
            asm volatile("cp.async.wait_group 0;\n" ::: "memory");
        }
        __syncthreads();

        // ---- S = Q K^T (single fp16) ----
        float sc[8][4];
#pragma unroll
        for (int nt = 0; nt < 8; nt++)
#pragma unroll
            for (int j = 0; j < 4; j++) sc[nt][j] = 0.0f;

#pragma unroll
        for (int kd = 0; kd < 8; kd++) {
            uint32_t ah[4];
            uint32_t qa = qh_base + kd * 32;
            ah[0] = lds_u32(qa);
            ah[1] = lds_u32(qa + 8 * 272);
            ah[2] = lds_u32(qa + 16);
            ah[3] = lds_u32(qa + 8 * 272 + 16);
#pragma unroll
            for (int nt = 0; nt < 8; nt++) {
                uint32_t kb = stg + STG_K + (nt * 8 + r) * 272 + kq * 2 + kd * 32;
                uint32_t bm[2] = {lds_u32(kb), lds_u32(kb + 16)};
                mma16816(sc[nt], ah, bm);
            }
        }

        // ---- causal mask ----
        if (kbase + FKT > q0) {
            const int row0g = q0 + wid * 16 + r;
#pragma unroll
            for (int nt = 0; nt < 8; nt++) {
                int key = kbase + nt * 8 + kq;
                if (key     > row0g)     sc[nt][0] = -1e30f;
                if (key + 1 > row0g)     sc[nt][1] = -1e30f;
                if (key     > row0g + 8) sc[nt][2] = -1e30f;
                if (key + 1 > row0g + 8) sc[nt][3] = -1e30f;
            }
        }

        // ---- online softmax ----
        float mx0 = -1e30f, mx1 = -1e30f;
#pragma unroll
        for (int nt = 0; nt < 8; nt++) {
            mx0 = fmaxf(mx0, fmaxf(sc[nt][0], sc[nt][1]));
            mx1 = fmaxf(mx1, fmaxf(sc[nt][2], sc[nt][3]));
        }
        mx0 = fmaxf(mx0, __shfl_xor_sync(0xffffffffu, mx0, 1));
        mx0 = fmaxf(mx0, __shfl_xor_sync(0xffffffffu, mx0, 2));
        mx1 = fmaxf(mx1, __shfl_xor_sync(0xffffffffu, mx1, 1));
        mx1 = fmaxf(mx1, __shfl_xor_sync(0xffffffffu, mx1, 2));
        float mn0 = fmaxf(m0, mx0), mn1 = fmaxf(m1, mx1);
        float c0 = __expf(m0 - mn0), c1 = __expf(m1 - mn1);
        float sum0 = 0.0f, sum1 = 0.0f;
#pragma unroll
        for (int nt = 0; nt < 8; nt++) {
            sc[nt][0] = __expf(sc[nt][0] - mn0); sum0 += sc[nt][0];
            sc[nt][1] = __expf(sc[nt][1] - mn0); sum0 += sc[nt][1];
            sc[nt][2] = __expf(sc[nt][2] - mn1); sum1 += sc[nt][2];
            sc[nt][3] = __expf(sc[nt][3] - mn1); sum1 += sc[nt][3];
        }
        sum0 += __shfl_xor_sync(0xffffffffu, sum0, 1);
        sum0 += __shfl_xor_sync(0xffffffffu, sum0, 2);
        sum1 += __shfl_xor_sync(0xffffffffu, sum1, 1);
        sum1 += __shfl_xor_sync(0xffffffffu, sum1, 2);
        l0 = l0 * c0 + sum0;  m0 = mn0;
        l1 = l1 * c1 + sum1;  m1 = mn1;
#pragma unroll
        for (int nt2 = 0; nt2 < 16; nt2++) {
            acc[nt2][0] *= c0; acc[nt2][1] *= c0;
            acc[nt2][2] *= c1; acc[nt2][3] *= c1;
        }

        // ---- O += P V (single fp16) ----
#pragma unroll
        for (int kk = 0; kk < 4; kk++) {
            uint32_t ph[4];
#pragma unroll
            for (int t4 = 0; t4 < 4; t4++) {
                int nt = 2 * kk + (t4 >> 1);
                ph[t4] = pack2h(sc[nt][(t4 & 1) * 2], sc[nt][(t4 & 1) * 2 + 1]);
            }
#pragma unroll
            for (int nt2 = 0; nt2 < 16; nt2++) {
                uint32_t vb = stg + STG_V + (nt2 * 8 + r) * 144 + (kk * 16 + kq) * 2;
                uint32_t bm[2] = {lds_u32(vb), lds_u32(vb + 16)};
                mma16816(acc[nt2], ph, bm);
            }
        }
        __syncthreads();
    }

    // ---- epilogue: normalize, write ctx fp16 ----
    float inv0 = 1.0f / l0, inv1 = 1.0f / l1;
    size_t row0 = (size_t)(b * SS + q0 + wid * 16 + r);
    size_t row1 = row0 + 8;
#pragma unroll
    for (int nt2 = 0; nt2 < 16; nt2++) {
        int d = h * DK + nt2 * 8 + kq;
        *(uint32_t*)&g_ch[row0 * HID + d] = pack2h(acc[nt2][0] * inv0, acc[nt2][1] * inv0);
        *(uint32_t*)&g_ch[row1 * HID + d] = pack2h(acc[nt2][2] * inv1, acc[nt2][3] * inv1);
    }
}

// ---------------------------------------------------------------------------
extern "C" void kernel_launch(void* const* d_in, const int* in_sizes, int n_in,
                              void* d_out, int out_size)
{
    const float* x       = (const float*)d_in[0];
    const float* w_q     = (const float*)d_in[1];
    const float* w_kv    = (const float*)d_in[2];
    const float* w_dense = (const float*)d_in[3];
    float* out = (float*)d_out;

    float* qkvp;
    __half *xh, *wqkv, *wd, *ch;
    cudaGetSymbolAddress((void**)&qkvp, g_qkv);
    cudaGetSymbolAddress((void**)&xh,   g_xh);
    cudaGetSymbolAddress((void**)&wqkv, g_wqkv);
    cudaGetSymbolAddress((void**)&wd,   g_wd);
    cudaGetSymbolAddress((void**)&ch,   g_ch);

    cudaFuncSetAttribute(gemm_mma, cudaFuncAttributeMaxDynamicSharedMemorySize, GEMM_SMEM);
    cudaFuncSetAttribute(flash_tc, cudaFuncAttributeMaxDynamicSharedMemorySize, FLASH_SMEM);

    // prep: convert x; transpose weights into combined [wq|wkv] buffer + wd
    prep_h<<<(BSTOK * KDIM / 4 + 255) / 256, 256>>>(x, xh, BSTOK * KDIM / 4);
    transpose_h<<<dim3(HID / 32, KDIM / 32), dim3(32, 8)>>>(w_q, wqkv, HID);
    transpose_h<<<dim3((2 * NG * DK) / 32, KDIM / 32), dim3(32, 8)>>>(w_kv, wqkv + (size_t)2048 * KDIM, 2 * NG * DK);
    transpose_h<<<dim3(HID / 32, KDIM / 32), dim3(32, 8)>>>(w_dense, wd, HID);

    // single QKV projection (fp32 out, plain epilogue)
    gemm_mma<<<dim3(NQKV / 128, BSTOK / 128), 256, GEMM_SMEM>>>(xh, wqkv, qkvp, NQKV);

    // merged rope (Q+K) and V transpose
    rope_qk<<<(BSTOK * (NH + NG) * 64) / 256, 256>>>();
    vt_h<<<dim3(SS / 32, DK / 32, BB * NG), dim3(32, 8)>>>();

    // attention (tensor cores, fp16)
    flash_tc<<<dim3(SS / FQT, NH, BB), 256, FLASH_SMEM>>>();

    // dense projection
    gemm_mma<<<dim3(HID / 128, BSTOK / 128), 256, GEMM_SMEM>>>(ch, wd, out, HID);
}

// round 17
// speedup vs baseline: 1.5406x; 1.0144x over previous
#include <cuda_runtime.h>
#include <cuda_fp16.h>
#include <cstdint>
#include <math.h>

#define BB    2
#define SS    2048
#define HID   2048
#define NH    16
#define NG    4
#define DK    128
#define NHPG  4
#define BSTOK (BB*SS)
#define KDIM  2048
#define NQKV  3072     // 2048 Q + 512 K + 512 V

// ---------------------------------------------------------------------------
// Scratch (__device__ globals; allocation-free rule)
// ---------------------------------------------------------------------------
static __device__ float  g_qkv [BSTOK * NQKV];         // QKV proj fp32 [tok][3072]

static __device__ __half g_xh  [BSTOK * KDIM];         // x fp16
static __device__ __half g_wqkv[NQKV * KDIM];          // [wq|wk|wv] transposed [N,K] fp16
static __device__ __half g_wd  [HID * KDIM];           // dense weights transposed fp16

static __device__ __half g_qh [BSTOK * HID];           // rope'd, pre-scaled Q fp16
static __device__ __half g_kh [BSTOK * NG * DK];       // rope'd K fp16 [tok][g*128+d]
static __device__ __half g_vth[BB * NG * DK * SS];     // V transposed fp16 [b,g][d][s]
static __device__ __half g_ch [BSTOK * KDIM];          // ctx fp16

// ---------------------------------------------------------------------------
// helpers (base-target safe)
// ---------------------------------------------------------------------------
__device__ __forceinline__ void cp_async16(uint32_t s, const void* g) {
    asm volatile("cp.async.cg.shared.global [%0], [%1], 16;\n" :: "r"(s), "l"(g) : "memory");
}
__device__ __forceinline__ void cp_commit() {
    asm volatile("cp.async.commit_group;\n" ::: "memory");
}
__device__ __forceinline__ uint32_t lds_u32(uint32_t a) {
    uint32_t v; asm("ld.shared.b32 %0, [%1];" : "=r"(v) : "r"(a)); return v;
}
__device__ __forceinline__ void ldsm4(uint32_t* r, uint32_t a) {
    asm volatile("ldmatrix.sync.aligned.m8n8.x4.shared.b16 {%0,%1,%2,%3}, [%4];"
        : "=r"(r[0]), "=r"(r[1]), "=r"(r[2]), "=r"(r[3]) : "r"(a));
}
__device__ __forceinline__ uint32_t pack2h(float lo, float hi) {
    __half2 h = __floats2half2_rn(lo, hi);
    return *(uint32_t*)&h;
}
__device__ __forceinline__ void mma16816(float* c, const uint32_t* a, const uint32_t* b)
{
    asm volatile(
        "mma.sync.aligned.m16n8k16.row.col.f32.f16.f16.f32 "
        "{%0,%1,%2,%3}, {%4,%5,%6,%7}, {%8,%9}, {%0,%1,%2,%3};"
        : "+f"(c[0]), "+f"(c[1]), "+f"(c[2]), "+f"(c[3])
        : "r"(a[0]), "r"(a[1]), "r"(a[2]), "r"(a[3]), "r"(b[0]), "r"(b[1]));
}

// ---------------------------------------------------------------------------
// Prep: fp32 -> fp16 convert
// ---------------------------------------------------------------------------
__global__ void prep_h(const float* __restrict__ src, __half* __restrict__ h, int n4)
{
    int i = blockIdx.x * blockDim.x + threadIdx.x;
    if (i >= n4) return;
    float4 v = ((const float4*)src)[i];
    __half hh[4] = {__float2half_rn(v.x), __float2half_rn(v.y),
                    __float2half_rn(v.z), __float2half_rn(v.w)};
    ((uint2*)h)[i] = *(uint2*)hh;
}

// ---------------------------------------------------------------------------
// Prep: transpose all three weight matrices in ONE launch.
// grid (64, KDIM/32, 3), block (32, 8). z: 0=w_q, 1=w_dense, 2=w_kv.
// ---------------------------------------------------------------------------
__global__ void transpose_all(const float* __restrict__ Wq,
                              const float* __restrict__ Wkv,
                              const float* __restrict__ Wd,
                              __half* __restrict__ Tqkv,
                              __half* __restrict__ Td)
{
    const int z = blockIdx.z;
    const float* W;
    __half* T;
    int Ncols;
    if (z == 0)      { W = Wq;  T = Tqkv;                        Ncols = HID; }
    else if (z == 1) { W = Wd;  T = Td;                          Ncols = HID; }
    else             { W = Wkv; T = Tqkv + (size_t)2048 * KDIM;  Ncols = 2 * NG * DK;
                       if (blockIdx.x >= (unsigned)(Ncols / 32)) return; }

    __shared__ float tile[32][33];
    int n = blockIdx.x * 32 + threadIdx.x;
    int k0 = blockIdx.y * 32;
#pragma unroll
    for (int r = 0; r < 4; r++) {
        int k = k0 + threadIdx.y + r * 8;
        tile[threadIdx.y + r * 8][threadIdx.x] = W[(size_t)k * Ncols + n];
    }
    __syncthreads();
#pragma unroll
    for (int r = 0; r < 4; r++) {
        int nn = blockIdx.x * 32 + threadIdx.y + r * 8;
        int kk = k0 + threadIdx.x;
        T[(size_t)nn * KDIM + kk] = __float2half_rn(tile[threadIdx.x][threadIdx.y + r * 8]);
    }
}

// ---------------------------------------------------------------------------
// mma.sync GEMM: C = A @ B, both single fp16, fp32 accum.
// Tile 128x128, 8 warps (2M x 4N), 3-stage cp.async + ldmatrix.
// __launch_bounds__(256, 2): force regs <= 128 so 2 CTAs/SM co-reside
// (2 x 110592 B smem = 216 KB <= 228 KB SM budget).
// ---------------------------------------------------------------------------
#define LDB    144
#define TILEB  (128 * LDB)
#define STAGEB (2 * TILEB)          // A | B
#define GEMM_SMEM (3 * STAGEB)      // 110592 B

__device__ __forceinline__ void load_chunk_mma(
    const __half* __restrict__ A, const __half* __restrict__ Bm,
    int m0, int n0, int k0, uint32_t stage, int tid)
{
#pragma unroll
    for (int i = 0; i < 8; i++) {
        int lin = i * 256 + tid;            // 0..2047
        int t   = lin >> 10;                // 0:A 1:B
        int rem = lin & 1023;
        int row = rem >> 3;
        int c   = rem & 7;
        const __half* base = t ? Bm : A;
        int grow = (t ? n0 : m0) + row;
        cp_async16(stage + t * TILEB + row * LDB + c * 16,
                   base + (size_t)grow * KDIM + k0 + c * 8);
    }
    cp_commit();
}

__global__ __launch_bounds__(256, 2) void gemm_mma(
    const __half* __restrict__ A, const __half* __restrict__ Bm,
    float* __restrict__ C, int N)
{
    extern __shared__ char smc[];
    uint32_t sb = (uint32_t)__cvta_generic_to_shared(smc);
    const int tid  = threadIdx.x;
    const int wid  = tid >> 5;
    const int lane = tid & 31;
    const int wm = wid >> 2;
    const int wn = wid & 3;
    const int m0 = blockIdx.y * 128;
    const int n0 = blockIdx.x * 128;
    const int r  = lane >> 2;
    const int kq = (lane & 3) * 2;

    const int qd = lane >> 3, lr = lane & 7;
    const uint32_t aBase = (uint32_t)((wm * 64 + (qd & 1) * 8 + lr) * LDB + (qd >> 1) * 16);
    const uint32_t bBase = (uint32_t)((wn * 32 + (qd >> 1) * 8 + lr) * LDB + (qd & 1) * 16);

    float acc[4][4][4];
#pragma unroll
    for (int mt = 0; mt < 4; mt++)
#pragma unroll
        for (int nt = 0; nt < 4; nt++)
#pragma unroll
            for (int j = 0; j < 4; j++) acc[mt][nt][j] = 0.0f;

    const int NC = KDIM / 64;           // 32
    load_chunk_mma(A, Bm, m0, n0, 0, sb, tid);
    load_chunk_mma(A, Bm, m0, n0, 64, sb + STAGEB, tid);

    for (int c = 0; c < NC; c++) {
        if (c + 1 < NC) {
            asm volatile("cp.async.wait_group 1;\n" ::: "memory");
        } else {
            asm volatile("cp.async.wait_group 0;\n" ::: "memory");
        }
        __syncthreads();
        if (c + 2 < NC)
            load_chunk_mma(A, Bm, m0, n0, (c + 2) * 64,
                           sb + (uint32_t)((c + 2) % 3) * STAGEB, tid);

        const uint32_t stg = sb + (uint32_t)(c % 3) * STAGEB;

#pragma unroll
        for (int ks = 0; ks < 4; ks++) {
            const uint32_t koff = (uint32_t)ks * 32;
            uint32_t ah[4][4], bm[2][4];
#pragma unroll
            for (int mt = 0; mt < 4; mt++)
                ldsm4(ah[mt], stg + aBase + (uint32_t)mt * (16 * LDB) + koff);
#pragma unroll
            for (int p = 0; p < 2; p++)
                ldsm4(bm[p], stg + TILEB + bBase + (uint32_t)p * (16 * LDB) + koff);

#pragma unroll
            for (int mt = 0; mt < 4; mt++)
#pragma unroll
                for (int nt = 0; nt < 4; nt++)
                    mma16816(acc[mt][nt], ah[mt], &bm[nt >> 1][(nt & 1) * 2]);
        }
    }

#pragma unroll
    for (int mt = 0; mt < 4; mt++) {
#pragma unroll
        for (int nt = 0; nt < 4; nt++) {
            int row = m0 + wm * 64 + mt * 16 + r;
            int col = n0 + wn * 32 + nt * 8 + kq;
            *(float2*)&C[(size_t)row * N + col]       = make_float2(acc[mt][nt][0], acc[mt][nt][1]);
            *(float2*)&C[(size_t)(row + 8) * N + col] = make_float2(acc[mt][nt][2], acc[mt][nt][3]);
        }
    }
}

// ---------------------------------------------------------------------------
// RoPE (Q and K merged) reading fp32 g_qkv, writing fp16 g_qh / g_kh
// ---------------------------------------------------------------------------
#define QSCALE 0.08838834764831845f

__global__ void rope_qk()
{
    int idx = blockIdx.x * blockDim.x + threadIdx.x;
    const int NQ = BSTOK * NH * 64;           // 4M Q pairs
    if (idx < NQ) {
        int j   = idx & 63;
        int h   = (idx >> 6) & (NH - 1);
        int tok = idx >> 10;
        int t = tok & (SS - 1);
        size_t src = (size_t)tok * NQKV + h * DK + j;
        float x1 = g_qkv[src], x2 = g_qkv[src + 64];
        float invf = exp2f(-0.20762050593045935f * (float)j);
        float f = (float)t * invf;
        float c, s;
        sincosf(f, &s, &c);
        size_t dst = (size_t)tok * HID + h * DK + j;
        g_qh[dst]      = __float2half_rn((x1 * c - x2 * s) * QSCALE);
        g_qh[dst + 64] = __float2half_rn((x2 * c + x1 * s) * QSCALE);
    } else {
        idx -= NQ;
        if (idx >= BSTOK * NG * 64) return;
        int j   = idx & 63;
        int g   = (idx >> 6) & (NG - 1);
        int tok = idx >> 8;
        int t = tok & (SS - 1);
        size_t src = (size_t)tok * NQKV + 2048 + g * DK + j;
        float x1 = g_qkv[src], x2 = g_qkv[src + 64];
        float invf = exp2f(-0.20762050593045935f * (float)j);
        float f = (float)t * invf;
        float c, s;
        sincosf(f, &s, &c);
        size_t dst = (size_t)tok * (NG * DK) + g * DK + j;
        g_kh[dst]      = __float2half_rn(x1 * c - x2 * s);
        g_kh[dst + 64] = __float2half_rn(x2 * c + x1 * s);
    }
}

// ---------------------------------------------------------------------------
// V transpose: fp32 g_qkv V-columns -> fp16 [b,g][d][s]
// ---------------------------------------------------------------------------
__global__ void vt_h()   // grid (SS/32, DK/32, BB*NG), block (32,8)
{
    __shared__ float tile[32][33];
    int bg = blockIdx.z;
    int b  = bg >> 2, g = bg & 3;
    int s0 = blockIdx.x * 32, d0 = blockIdx.y * 32;
#pragma unroll
    for (int r = 0; r < 4; r++) {
        int s = s0 + threadIdx.y + r * 8;
        tile[threadIdx.y + r * 8][threadIdx.x] =
            g_qkv[(size_t)(b * SS + s) * NQKV + 2560 + g * DK + d0 + threadIdx.x];
    }
    __syncthreads();
#pragma unroll
    for (int r = 0; r < 4; r++) {
        int d = d0 + threadIdx.y + r * 8;
        int s = s0 + threadIdx.x;
        size_t dst = ((size_t)bg * DK + d) * SS + s;
        g_vth[dst] = __float2half_rn(tile[threadIdx.x][threadIdx.y + r * 8]);
    }
}

// ---------------------------------------------------------------------------
// Flash attention fp16: QK 1 term, PV 1 term, causal. fp32 softmax/accum.
// Block: 256 thr = 8 warps, each warp 16 query rows. 128 q x 64 k tiles.
// ---------------------------------------------------------------------------
#define FQT 128
#define FKT 64
#define OFF_Q  0
#define STG0   (FQT*272)                 // 34816
#define STG_K  0
#define STG_V  (FKT*272)                 // 17408
#define STG_SZ (FKT*272 + FQT*144)       // 35840
#define FLASH_SMEM (STG0 + 2*STG_SZ)     // 106496

__device__ __forceinline__ void flash_load_kv(int b, int g, int kbase, uint32_t stg, int tid)
{
#pragma unroll
    for (int i = 0; i < 8; i++) {
        int lin = i * 256 + tid;
        if (lin < 1024) {                 // K tile: 64 rows x 16 chunks
            int row = lin >> 4, c = lin & 15;
            const __half* src = g_kh
                + (size_t)(b * SS + kbase + row) * (NG * DK) + g * DK + c * 8;
            cp_async16(stg + STG_K + row * 272 + c * 16, src);
        } else {                          // Vt tile: 128 rows x 8 chunks
            int lin2 = lin - 1024;
            int row = lin2 >> 3, c = lin2 & 7;
            const __half* src = g_vth
                + ((size_t)(b * NG + g) * DK + row) * SS + kbase + c * 8;
            cp_async16(stg + STG_V + row * 144 + c * 16, src);
        }
    }
    cp_commit();
}

__global__ __launch_bounds__(256) void flash_tc()
{
    extern __shared__ char smc[];
    uint32_t sb = (uint32_t)__cvta_generic_to_shared(smc);
    const int tid  = threadIdx.x;
    const int wid  = tid >> 5;
    const int lane = tid & 31;
    const int qt = gridDim.x - 1 - blockIdx.x;    // heavy tiles first
    const int h  = blockIdx.y;
    const int b  = blockIdx.z;
    const int g  = h / NHPG;
    const int q0 = qt * FQT;
    const int r  = lane >> 2;
    const int kq = (lane & 3) * 2;

    // load Q tile (once): 128 rows x 16 chunks = 2048
#pragma unroll
    for (int i = 0; i < 8; i++) {
        int lin = i * 256 + tid;
        int row = lin >> 4, c = lin & 15;
        const __half* src = g_qh + (size_t)(b * SS + q0 + row) * HID + h * DK + c * 8;
        cp_async16(sb + OFF_Q + row * 272 + c * 16, src);
    }
    cp_commit();

    const int numc = 2 * (qt + 1);
    flash_load_kv(b, g, 0, sb + STG0, tid);

    float m0 = -1e30f, m1 = -1e30f, l0 = 0.0f, l1 = 0.0f;
    float acc[16][4];
#pragma unroll
    for (int nt2 = 0; nt2 < 16; nt2++)
#pragma unroll
        for (int j = 0; j < 4; j++) acc[nt2][j] = 0.0f;

    const uint32_t qh_base = sb + OFF_Q + (wid * 16 + r) * 272 + kq * 2;

    for (int kc = 0; kc < numc; kc++) {
        const uint32_t stg = sb + STG0 + (uint32_t)(kc & 1) * STG_SZ;
        const int kbase = kc * FKT;
        if (kc + 1 < numc) {
            flash_load_kv(b, g, (kc + 1) * FKT, sb + STG0 + (uint32_t)((kc + 1) & 1) * STG_SZ, tid);
            asm volatile("cp.async.wait_group 1;\n" ::: "memory");
        } else {
            asm volatile("cp.async.wait_group 0;\n" ::: "memory");
        }
        __syncthreads();

        // ---- S = Q K^T (single fp16) ----
        float sc[8][4];
#pragma unroll
        for (int nt = 0; nt < 8; nt++)
#pragma unroll
            for (int j = 0; j < 4; j++) sc[nt][j] = 0.0f;

#pragma unroll
        for (int kd = 0; kd < 8; kd++) {
            uint32_t ah[4];
            uint32_t qa = qh_base + kd * 32;
            ah[0] = lds_u32(qa);
            ah[1] = lds_u32(qa + 8 * 272);
            ah[2] = lds_u32(qa + 16);
            ah[3] = lds_u32(qa + 8 * 272 + 16);
#pragma unroll
            for (int nt = 0; nt < 8; nt++) {
                uint32_t kb = stg + STG_K + (nt * 8 + r) * 272 + kq * 2 + kd * 32;
                uint32_t bm[2] = {lds_u32(kb), lds_u32(kb + 16)};
                mma16816(sc[nt], ah, bm);
            }
        }

        // ---- causal mask ----
        if (kbase + FKT > q0) {
            const int row0g = q0 + wid * 16 + r;
#pragma unroll
            for (int nt = 0; nt < 8; nt++) {
                int key = kbase + nt * 8 + kq;
                if (key     > row0g)     sc[nt][0] = -1e30f;
                if (key + 1 > row0g)     sc[nt][1] = -1e30f;
                if (key     > row0g + 8) sc[nt][2] = -1e30f;
                if (key + 1 > row0g + 8) sc[nt][3] = -1e30f;
            }
        }

        // ---- online softmax ----
        float mx0 = -1e30f, mx1 = -1e30f;
#pragma unroll
        for (int nt = 0; nt < 8; nt++) {
            mx0 = fmaxf(mx0, fmaxf(sc[nt][0], sc[nt][1]));
            mx1 = fmaxf(mx1, fmaxf(sc[nt][2], sc[nt][3]));
        }
        mx0 = fmaxf(mx0, __shfl_xor_sync(0xffffffffu, mx0, 1));
        mx0 = fmaxf(mx0, __shfl_xor_sync(0xffffffffu, mx0, 2));
        mx1 = fmaxf(mx1, __shfl_xor_sync(0xffffffffu, mx1, 1));
        mx1 = fmaxf(mx1, __shfl_xor_sync(0xffffffffu, mx1, 2));
        float mn0 = fmaxf(m0, mx0), mn1 = fmaxf(m1, mx1);
        float c0 = __expf(m0 - mn0), c1 = __expf(m1 - mn1);
        float sum0 = 0.0f, sum1 = 0.0f;
#pragma unroll
        for (int nt = 0; nt < 8; nt++) {
            sc[nt][0] = __expf(sc[nt][0] - mn0); sum0 += sc[nt][0];
            sc[nt][1] = __expf(sc[nt][1] - mn0); sum0 += sc[nt][1];
            sc[nt][2] = __expf(sc[nt][2] - mn1); sum1 += sc[nt][2];
            sc[nt][3] = __expf(sc[nt][3] - mn1); sum1 += sc[nt][3];
        }
        sum0 += __shfl_xor_sync(0xffffffffu, sum0, 1);
        sum0 += __shfl_xor_sync(0xffffffffu, sum0, 2);
        sum1 += __shfl_xor_sync(0xffffffffu, sum1, 1);
        sum1 += __shfl_xor_sync(0xffffffffu, sum1, 2);
        l0 = l0 * c0 + sum0;  m0 = mn0;
        l1 = l1 * c1 + sum1;  m1 = mn1;
#pragma unroll
        for (int nt2 = 0; nt2 < 16; nt2++) {
            acc[nt2][0] *= c0; acc[nt2][1] *= c0;
            acc[nt2][2] *= c1; acc[nt2][3] *= c1;
        }

        // ---- O += P V (single fp16) ----
#pragma unroll
        for (int kk = 0; kk < 4; kk++) {
            uint32_t ph[4];
#pragma unroll
            for (int t4 = 0; t4 < 4; t4++) {
                int nt = 2 * kk + (t4 >> 1);
                ph[t4] = pack2h(sc[nt][(t4 & 1) * 2], sc[nt][(t4 & 1) * 2 + 1]);
            }
#pragma unroll
            for (int nt2 = 0; nt2 < 16; nt2++) {
                uint32_t vb = stg + STG_V + (nt2 * 8 + r) * 144 + (kk * 16 + kq) * 2;
                uint32_t bm[2] = {lds_u32(vb), lds_u32(vb + 16)};
                mma16816(acc[nt2], ph, bm);
            }
        }
        __syncthreads();
    }

    // ---- epilogue: normalize, write ctx fp16 ----
    float inv0 = 1.0f / l0, inv1 = 1.0f / l1;
    size_t row0 = (size_t)(b * SS + q0 + wid * 16 + r);
    size_t row1 = row0 + 8;
#pragma unroll
    for (int nt2 = 0; nt2 < 16; nt2++) {
        int d = h * DK + nt2 * 8 + kq;
        *(uint32_t*)&g_ch[row0 * HID + d] = pack2h(acc[nt2][0] * inv0, acc[nt2][1] * inv0);
        *(uint32_t*)&g_ch[row1 * HID + d] = pack2h(acc[nt2][2] * inv1, acc[nt2][3] * inv1);
    }
}

// ---------------------------------------------------------------------------
extern "C" void kernel_launch(void* const* d_in, const int* in_sizes, int n_in,
                              void* d_out, int out_size)
{
    const float* x       = (const float*)d_in[0];
    const float* w_q     = (const float*)d_in[1];
    const float* w_kv    = (const float*)d_in[2];
    const float* w_dense = (const float*)d_in[3];
    float* out = (float*)d_out;

    float* qkvp;
    __half *xh, *wqkv, *wd, *ch;
    cudaGetSymbolAddress((void**)&qkvp, g_qkv);
    cudaGetSymbolAddress((void**)&xh,   g_xh);
    cudaGetSymbolAddress((void**)&wqkv, g_wqkv);
    cudaGetSymbolAddress((void**)&wd,   g_wd);
    cudaGetSymbolAddress((void**)&ch,   g_ch);

    cudaFuncSetAttribute(gemm_mma, cudaFuncAttributeMaxDynamicSharedMemorySize, GEMM_SMEM);
    cudaFuncSetAttribute(flash_tc, cudaFuncAttributeMaxDynamicSharedMemorySize, FLASH_SMEM);

    // prep: convert x; transpose all weights in one launch
    prep_h<<<(BSTOK * KDIM / 4 + 255) / 256, 256>>>(x, xh, BSTOK * KDIM / 4);
    transpose_all<<<dim3(HID / 32, KDIM / 32, 3), dim3(32, 8)>>>(w_q, w_kv, w_dense, wqkv, wd);

    // single QKV projection (fp32 out, plain epilogue)
    gemm_mma<<<dim3(NQKV / 128, BSTOK / 128), 256, GEMM_SMEM>>>(xh, wqkv, qkvp, NQKV);

    // merged rope (Q+K) and V transpose
    rope_qk<<<(BSTOK * (NH + NG) * 64) / 256, 256>>>();
    vt_h<<<dim3(SS / 32, DK / 32, BB * NG), dim3(32, 8)>>>();

    // attention (tensor cores, fp16)
    flash_tc<<<dim3(SS / FQT, NH, BB), 256, FLASH_SMEM>>>();

    // dense projection
    gemm_mma<<<dim3(HID / 128, BSTOK / 128), 256, GEMM_SMEM>>>(ch, wd, out, HID);
}